// round 7
// baseline (speedup 1.0000x reference)
#include <cuda_runtime.h>
#include <cuda_fp16.h>
#include <cstdint>

#define N_NODES 50000
#define N_EDGES 1600000
#define D_FEAT  128
#define NH4     (D_FEAT / 8)   // 16 uint4 (8 halfs) per fp16 row

#define SCAN_CHUNK   1024
#define SCAN_BLOCKS  ((N_NODES + SCAN_CHUNK - 1) / SCAN_CHUNK)   // 49

// Scratch (no cudaMalloc allowed).
__device__ uint4 g_xh      [(size_t)N_NODES * NH4];   // fp16 copy of gather operand
__device__ uint4 g_scratchh[(size_t)N_NODES * NH4];   // fp16 round-1 result
__device__ int   g_counts  [N_NODES];                 // zero at every call entry
__device__ int   g_row_ptr [N_NODES + 1];             // chunk-local exclusive scan
__device__ int   g_eoff    [N_EDGES];
__device__ int2  g_edges   [N_EDGES];                 // packed (col, val-bits)
__device__ int   g_partials[SCAN_BLOCKS];
__device__ int   g_poffs   [SCAN_BLOCKS];             // per-chunk global offset

// ---------------- fp32 -> fp16 conversion (8 feats / thread) ----------------
__global__ void conv_kernel(const float4* __restrict__ in, uint4* __restrict__ out, int n) {
    int i = blockIdx.x * blockDim.x + threadIdx.x;
    if (i >= n) return;
    float4 f0 = in[2 * i];
    float4 f1 = in[2 * i + 1];
    __half2 h0 = __float22half2_rn(make_float2(f0.x, f0.y));
    __half2 h1 = __float22half2_rn(make_float2(f0.z, f0.w));
    __half2 h2 = __float22half2_rn(make_float2(f1.x, f1.y));
    __half2 h3 = __float22half2_rn(make_float2(f1.z, f1.w));
    uint4 o;
    o.x = *reinterpret_cast<unsigned*>(&h0);
    o.y = *reinterpret_cast<unsigned*>(&h1);
    o.z = *reinterpret_cast<unsigned*>(&h2);
    o.w = *reinterpret_cast<unsigned*>(&h3);
    out[i] = o;
}

// ---------------- CSR build ----------------
// Histogram + record each edge's rank within its row.
__global__ void hist_kernel(const int* __restrict__ adj_row, int* __restrict__ counts,
                            int* __restrict__ eoff, int n_edges) {
    int e = blockIdx.x * blockDim.x + threadIdx.x;
    if (e >= n_edges) return;
    eoff[e] = atomicAdd(&counts[adj_row[e]], 1);
}

// Chunk-local exclusive scan; also restores counts to zero for the next call.
__global__ void __launch_bounds__(1024) scan_block_kernel(
    int* __restrict__ counts, int* __restrict__ row_ptr,
    int* __restrict__ partials)
{
    __shared__ int warp_sums[32];
    const int tid  = threadIdx.x;
    const int lane = tid & 31;
    const int wid  = tid >> 5;
    const int i    = blockIdx.x * SCAN_CHUNK + tid;

    int v = 0;
    if (i < N_NODES) {
        v = counts[i];
        counts[i] = 0;          // restore invariant (replaces zero_counts kernel)
    }

    int incl = v;
    #pragma unroll
    for (int off = 1; off < 32; off <<= 1) {
        int t = __shfl_up_sync(0xffffffffu, incl, off);
        if (lane >= off) incl += t;
    }
    if (lane == 31) warp_sums[wid] = incl;
    __syncthreads();

    if (wid == 0) {
        int s = warp_sums[lane];
        int si = s;
        #pragma unroll
        for (int off = 1; off < 32; off <<= 1) {
            int t = __shfl_up_sync(0xffffffffu, si, off);
            if (lane >= off) si += t;
        }
        warp_sums[lane] = si - s;
    }
    __syncthreads();

    int excl = incl - v + warp_sums[wid];
    if (i < N_NODES) row_ptr[i] = excl;                 // chunk-local
    if (tid == SCAN_CHUNK - 1) partials[blockIdx.x] = excl + v;
}

// Scan the 49 chunk totals -> per-chunk offsets. row_ptr[N] is written so that
// row_ptr[N] + poffs[N>>10] == grand total (uniform formula for consumers).
__global__ void scan_partials_kernel(const int* __restrict__ partials,
                                     int* __restrict__ poffs,
                                     int* __restrict__ row_ptr)
{
    __shared__ int warp_sums[2];
    const int tid  = threadIdx.x;    // 64 threads
    const int lane = tid & 31;
    const int wid  = tid >> 5;

    int v = (tid < SCAN_BLOCKS) ? partials[tid] : 0;
    int incl = v;
    #pragma unroll
    for (int off = 1; off < 32; off <<= 1) {
        int t = __shfl_up_sync(0xffffffffu, incl, off);
        if (lane >= off) incl += t;
    }
    if (lane == 31) warp_sums[wid] = incl;
    __syncthreads();
    int wadd = (wid == 1) ? warp_sums[0] : 0;
    int excl = incl - v + wadd;
    if (tid < SCAN_BLOCKS) poffs[tid] = excl;
    if (tid == SCAN_BLOCKS - 1)
        row_ptr[N_NODES] = (excl + v) - excl;   // total - poffs[last chunk]
}

// Place packed (col, val) at global position. One 8B random write/edge.
__global__ void scatter_kernel(const int* __restrict__ adj_row,
                               const int* __restrict__ adj_col,
                               const float* __restrict__ adj_vals,
                               const int* __restrict__ row_ptr,
                               const int* __restrict__ poffs,
                               const int* __restrict__ eoff,
                               int2* __restrict__ edges,
                               int n_edges) {
    int e = blockIdx.x * blockDim.x + threadIdx.x;
    if (e >= n_edges) return;
    int r = adj_row[e];
    int p = __ldg(row_ptr + r) + __ldg(poffs + (r >> 10)) + eoff[e];
    edges[p] = make_int2(adj_col[e], __float_as_int(adj_vals[e]));
}

// ---------------- CSR SpMM: warp/row, half-warp/edge, fp16 gather ------------
template <int OUT_HALF>
__global__ void __launch_bounds__(256) spmm_csr_h_kernel(
    const uint4* __restrict__ xh,
    const int*   __restrict__ row_ptr,
    const int*   __restrict__ poffs,
    const int2*  __restrict__ edges,
    void*        __restrict__ out)
{
    int row  = (blockIdx.x * blockDim.x + threadIdx.x) >> 5;
    int lane = threadIdx.x & 31;
    if (row >= N_NODES) return;

    const int hlane = lane & 15;        // lane within half-warp
    const int half  = lane >> 4;        // 0 or 1

    int start = __ldg(row_ptr + row)     + __ldg(poffs + (row >> 10));
    int end   = __ldg(row_ptr + row + 1) + __ldg(poffs + ((row + 1) >> 10));

    float acc[8] = {0.f, 0.f, 0.f, 0.f, 0.f, 0.f, 0.f, 0.f};

    for (int base = start; base < end; base += 32) {
        int n = end - base;
        if (n > 32) n = 32;
        int2 ep = make_int2(0, 0);
        if (lane < n) ep = __ldg(edges + base + lane);

        #pragma unroll 4
        for (int j = 0; j < n; j += 2) {
            int je = j + half;
            int cj = __shfl_sync(0xffffffffu, ep.x, je);
            int vb = __shfl_sync(0xffffffffu, ep.y, je);
            if (je >= n) { cj = 0; vb = 0; }      // zero-weight read of row 0
            float vj = __int_as_float(vb);

            uint4 m = __ldg(xh + (size_t)cj * NH4 + hlane);
            __half2 h0 = *reinterpret_cast<__half2*>(&m.x);
            __half2 h1 = *reinterpret_cast<__half2*>(&m.y);
            __half2 h2 = *reinterpret_cast<__half2*>(&m.z);
            __half2 h3 = *reinterpret_cast<__half2*>(&m.w);
            float2 f0 = __half22float2(h0);
            float2 f1 = __half22float2(h1);
            float2 f2 = __half22float2(h2);
            float2 f3 = __half22float2(h3);
            acc[0] = fmaf(vj, f0.x, acc[0]);
            acc[1] = fmaf(vj, f0.y, acc[1]);
            acc[2] = fmaf(vj, f1.x, acc[2]);
            acc[3] = fmaf(vj, f1.y, acc[3]);
            acc[4] = fmaf(vj, f2.x, acc[4]);
            acc[5] = fmaf(vj, f2.y, acc[5]);
            acc[6] = fmaf(vj, f3.x, acc[6]);
            acc[7] = fmaf(vj, f3.y, acc[7]);
        }
    }

    #pragma unroll
    for (int k = 0; k < 8; k++)
        acc[k] += __shfl_xor_sync(0xffffffffu, acc[k], 16);

    if (half == 0) {
        if (OUT_HALF) {
            __half2 h0 = __float22half2_rn(make_float2(acc[0], acc[1]));
            __half2 h1 = __float22half2_rn(make_float2(acc[2], acc[3]));
            __half2 h2 = __float22half2_rn(make_float2(acc[4], acc[5]));
            __half2 h3 = __float22half2_rn(make_float2(acc[6], acc[7]));
            uint4 o;
            o.x = *reinterpret_cast<unsigned*>(&h0);
            o.y = *reinterpret_cast<unsigned*>(&h1);
            o.z = *reinterpret_cast<unsigned*>(&h2);
            o.w = *reinterpret_cast<unsigned*>(&h3);
            reinterpret_cast<uint4*>(out)[(size_t)row * NH4 + hlane] = o;
        } else {
            float4* o4 = reinterpret_cast<float4*>(out) + (size_t)row * (D_FEAT / 4) + hlane * 2;
            o4[0] = make_float4(acc[0], acc[1], acc[2], acc[3]);
            o4[1] = make_float4(acc[4], acc[5], acc[6], acc[7]);
        }
    }
}

// ---------------- launch ----------------
extern "C" void kernel_launch(void* const* d_in, const int* in_sizes, int n_in,
                              void* d_out, int out_size) {
    const float* x        = (const float*)d_in[0];
    const int*   adj_row  = (const int*)  d_in[1];
    const int*   adj_col  = (const int*)  d_in[2];
    const float* adj_vals = (const float*)d_in[3];
    float*       out      = (float*)d_out;

    int n_edges = in_sizes[1];

    uint4 *xh, *scratchh; int *counts, *row_ptr, *eoff, *partials, *poffs; int2 *edges;
    cudaGetSymbolAddress((void**)&xh,       g_xh);
    cudaGetSymbolAddress((void**)&scratchh, g_scratchh);
    cudaGetSymbolAddress((void**)&counts,   g_counts);
    cudaGetSymbolAddress((void**)&row_ptr,  g_row_ptr);
    cudaGetSymbolAddress((void**)&eoff,     g_eoff);
    cudaGetSymbolAddress((void**)&partials, g_partials);
    cudaGetSymbolAddress((void**)&poffs,    g_poffs);
    cudaGetSymbolAddress((void**)&edges,    g_edges);

    const int T = 256;

    // CSR build + fp16 conversion of x. (counts is zero at entry; scan restores it.)
    hist_kernel<<<(n_edges + T - 1) / T, T>>>(adj_row, counts, eoff, n_edges);
    const int nconv = N_NODES * NH4;
    conv_kernel<<<(nconv + T - 1) / T, T>>>((const float4*)x, xh, nconv);

    scan_block_kernel<<<SCAN_BLOCKS, SCAN_CHUNK>>>(counts, row_ptr, partials);
    scan_partials_kernel<<<1, 64>>>(partials, poffs, row_ptr);

    scatter_kernel<<<(n_edges + T - 1) / T, T>>>(adj_row, adj_col, adj_vals,
                                                 row_ptr, poffs, eoff, edges, n_edges);

    // Two propagation rounds.
    const int WPB = T / 32;
    const int sb = (N_NODES + WPB - 1) / WPB;
    spmm_csr_h_kernel<1><<<sb, T>>>(xh, row_ptr, poffs, edges, scratchh);
    spmm_csr_h_kernel<0><<<sb, T>>>(scratchh, row_ptr, poffs, edges, out);
}

// round 8
// speedup vs baseline: 1.3612x; 1.3612x over previous
#include <cuda_runtime.h>
#include <cuda_fp16.h>
#include <cstdint>

#define N_NODES 50000
#define N_EDGES 1600000
#define D_FEAT  128
#define NH4     (D_FEAT / 8)   // 16 uint4 (8 halfs) per fp16 row

#define SCAN_CHUNK   1024
#define SCAN_BLOCKS  ((N_NODES + SCAN_CHUNK - 1) / SCAN_CHUNK)   // 49

// Scratch (no cudaMalloc allowed).
__device__ uint4 g_xh      [(size_t)N_NODES * NH4];   // fp16 copy of gather operand
__device__ uint4 g_scratchh[(size_t)N_NODES * NH4];   // fp16 round-1 result
__device__ int   g_counts  [N_NODES];                 // zero at every call entry
__device__ int   g_row_ptr [N_NODES + 1];             // chunk-local exclusive scan
__device__ int   g_eoff    [N_EDGES];
__device__ int2  g_edges   [N_EDGES];                 // packed (col, val-bits)
__device__ int   g_partials[SCAN_BLOCKS];             // per-chunk totals

// ---- per-block inline exclusive scan of the 49 chunk totals into SMEM ------
// Must be called by ALL threads of a >=64-thread block (contains syncthreads).
__device__ __forceinline__ void block_scan_partials(
    const int* __restrict__ partials, int* s_poffs /* [SCAN_BLOCKS] */,
    int* s_wsum /* [2] */)
{
    const int tid = threadIdx.x;
    int p_incl = 0, p_v = 0;
    if (tid < 64) {
        const int lane = tid & 31;
        p_v = (tid < SCAN_BLOCKS) ? __ldg(partials + tid) : 0;
        p_incl = p_v;
        #pragma unroll
        for (int off = 1; off < 32; off <<= 1) {
            int t = __shfl_up_sync(0xffffffffu, p_incl, off);
            if (lane >= off) p_incl += t;
        }
        if (lane == 31) s_wsum[tid >> 5] = p_incl;
    }
    __syncthreads();
    if (tid < SCAN_BLOCKS) {
        int wadd = (tid >= 32) ? s_wsum[0] : 0;
        s_poffs[tid] = p_incl - p_v + wadd;   // exclusive prefix
    }
    __syncthreads();
}

// ---------------- fp32 -> fp16 conversion (8 feats / thread) ----------------
__global__ void conv_kernel(const float4* __restrict__ in, uint4* __restrict__ out, int n) {
    int i = blockIdx.x * blockDim.x + threadIdx.x;
    if (i >= n) return;
    float4 f0 = in[2 * i];
    float4 f1 = in[2 * i + 1];
    __half2 h0 = __float22half2_rn(make_float2(f0.x, f0.y));
    __half2 h1 = __float22half2_rn(make_float2(f0.z, f0.w));
    __half2 h2 = __float22half2_rn(make_float2(f1.x, f1.y));
    __half2 h3 = __float22half2_rn(make_float2(f1.z, f1.w));
    uint4 o;
    o.x = *reinterpret_cast<unsigned*>(&h0);
    o.y = *reinterpret_cast<unsigned*>(&h1);
    o.z = *reinterpret_cast<unsigned*>(&h2);
    o.w = *reinterpret_cast<unsigned*>(&h3);
    out[i] = o;
}

// ---------------- CSR build ----------------
// Histogram + record each edge's rank within its row.
__global__ void hist_kernel(const int* __restrict__ adj_row, int* __restrict__ counts,
                            int* __restrict__ eoff, int n_edges) {
    int e = blockIdx.x * blockDim.x + threadIdx.x;
    if (e >= n_edges) return;
    eoff[e] = atomicAdd(&counts[adj_row[e]], 1);
}

// Chunk-local exclusive scan; restores counts to zero; writes row_ptr[N] too.
__global__ void __launch_bounds__(1024) scan_block_kernel(
    int* __restrict__ counts, int* __restrict__ row_ptr,
    int* __restrict__ partials)
{
    __shared__ int warp_sums[32];
    const int tid  = threadIdx.x;
    const int lane = tid & 31;
    const int wid  = tid >> 5;
    const int i    = blockIdx.x * SCAN_CHUNK + tid;

    int v = 0;
    if (i < N_NODES) {
        v = counts[i];
        counts[i] = 0;          // restore invariant (replaces zero_counts kernel)
    }

    int incl = v;
    #pragma unroll
    for (int off = 1; off < 32; off <<= 1) {
        int t = __shfl_up_sync(0xffffffffu, incl, off);
        if (lane >= off) incl += t;
    }
    if (lane == 31) warp_sums[wid] = incl;
    __syncthreads();

    if (wid == 0) {
        int s = warp_sums[lane];
        int si = s;
        #pragma unroll
        for (int off = 1; off < 32; off <<= 1) {
            int t = __shfl_up_sync(0xffffffffu, si, off);
            if (lane >= off) si += t;
        }
        warp_sums[lane] = si - s;
    }
    __syncthreads();

    int excl = incl - v + warp_sums[wid];
    if (i <= N_NODES) row_ptr[i] = excl;                // includes i == N_NODES
    if (tid == SCAN_CHUNK - 1) partials[blockIdx.x] = excl + v;
}

// Place packed (col, val) at global position. One 8B random write/edge.
__global__ void __launch_bounds__(256) scatter_kernel(
    const int* __restrict__ adj_row,
    const int* __restrict__ adj_col,
    const float* __restrict__ adj_vals,
    const int* __restrict__ row_ptr,
    const int* __restrict__ partials,
    const int* __restrict__ eoff,
    int2* __restrict__ edges,
    int n_edges)
{
    __shared__ int s_poffs[SCAN_BLOCKS];
    __shared__ int s_wsum[2];
    block_scan_partials(partials, s_poffs, s_wsum);

    int e = blockIdx.x * blockDim.x + threadIdx.x;
    if (e >= n_edges) return;
    int r = adj_row[e];
    int p = __ldg(row_ptr + r) + s_poffs[r >> 10] + eoff[e];
    edges[p] = make_int2(adj_col[e], __float_as_int(adj_vals[e]));
}

// ---------------- CSR SpMM: warp/row, half-warp/edge, fp16 gather ------------
template <int OUT_HALF>
__global__ void __launch_bounds__(256) spmm_csr_h_kernel(
    const uint4* __restrict__ xh,
    const int*   __restrict__ row_ptr,
    const int*   __restrict__ partials,
    const int2*  __restrict__ edges,
    void*        __restrict__ out)
{
    __shared__ int s_poffs[SCAN_BLOCKS];
    __shared__ int s_wsum[2];
    block_scan_partials(partials, s_poffs, s_wsum);

    int row  = (blockIdx.x * blockDim.x + threadIdx.x) >> 5;
    int lane = threadIdx.x & 31;
    if (row >= N_NODES) return;

    const int hlane = lane & 15;        // lane within half-warp
    const int half  = lane >> 4;        // 0 or 1

    int start = __ldg(row_ptr + row)     + s_poffs[row >> 10];
    int end   = __ldg(row_ptr + row + 1) + s_poffs[(row + 1) >> 10];

    float acc[8] = {0.f, 0.f, 0.f, 0.f, 0.f, 0.f, 0.f, 0.f};

    for (int base = start; base < end; base += 32) {
        int n = end - base;
        if (n > 32) n = 32;
        int2 ep = make_int2(0, 0);
        if (lane < n) ep = __ldg(edges + base + lane);

        #pragma unroll 4
        for (int j = 0; j < n; j += 2) {
            int je = j + half;
            int cj = __shfl_sync(0xffffffffu, ep.x, je);
            int vb = __shfl_sync(0xffffffffu, ep.y, je);
            if (je >= n) { cj = 0; vb = 0; }      // zero-weight read of row 0
            float vj = __int_as_float(vb);

            uint4 m = __ldg(xh + (size_t)cj * NH4 + hlane);
            __half2 h0 = *reinterpret_cast<__half2*>(&m.x);
            __half2 h1 = *reinterpret_cast<__half2*>(&m.y);
            __half2 h2 = *reinterpret_cast<__half2*>(&m.z);
            __half2 h3 = *reinterpret_cast<__half2*>(&m.w);
            float2 f0 = __half22float2(h0);
            float2 f1 = __half22float2(h1);
            float2 f2 = __half22float2(h2);
            float2 f3 = __half22float2(h3);
            acc[0] = fmaf(vj, f0.x, acc[0]);
            acc[1] = fmaf(vj, f0.y, acc[1]);
            acc[2] = fmaf(vj, f1.x, acc[2]);
            acc[3] = fmaf(vj, f1.y, acc[3]);
            acc[4] = fmaf(vj, f2.x, acc[4]);
            acc[5] = fmaf(vj, f2.y, acc[5]);
            acc[6] = fmaf(vj, f3.x, acc[6]);
            acc[7] = fmaf(vj, f3.y, acc[7]);
        }
    }

    #pragma unroll
    for (int k = 0; k < 8; k++)
        acc[k] += __shfl_xor_sync(0xffffffffu, acc[k], 16);

    if (half == 0) {
        if (OUT_HALF) {
            __half2 h0 = __float22half2_rn(make_float2(acc[0], acc[1]));
            __half2 h1 = __float22half2_rn(make_float2(acc[2], acc[3]));
            __half2 h2 = __float22half2_rn(make_float2(acc[4], acc[5]));
            __half2 h3 = __float22half2_rn(make_float2(acc[6], acc[7]));
            uint4 o;
            o.x = *reinterpret_cast<unsigned*>(&h0);
            o.y = *reinterpret_cast<unsigned*>(&h1);
            o.z = *reinterpret_cast<unsigned*>(&h2);
            o.w = *reinterpret_cast<unsigned*>(&h3);
            reinterpret_cast<uint4*>(out)[(size_t)row * NH4 + hlane] = o;
        } else {
            float4* o4 = reinterpret_cast<float4*>(out) + (size_t)row * (D_FEAT / 4) + hlane * 2;
            o4[0] = make_float4(acc[0], acc[1], acc[2], acc[3]);
            o4[1] = make_float4(acc[4], acc[5], acc[6], acc[7]);
        }
    }
}

// ---------------- launch ----------------
extern "C" void kernel_launch(void* const* d_in, const int* in_sizes, int n_in,
                              void* d_out, int out_size) {
    const float* x        = (const float*)d_in[0];
    const int*   adj_row  = (const int*)  d_in[1];
    const int*   adj_col  = (const int*)  d_in[2];
    const float* adj_vals = (const float*)d_in[3];
    float*       out      = (float*)d_out;

    int n_edges = in_sizes[1];

    uint4 *xh, *scratchh; int *counts, *row_ptr, *eoff, *partials; int2 *edges;
    cudaGetSymbolAddress((void**)&xh,       g_xh);
    cudaGetSymbolAddress((void**)&scratchh, g_scratchh);
    cudaGetSymbolAddress((void**)&counts,   g_counts);
    cudaGetSymbolAddress((void**)&row_ptr,  g_row_ptr);
    cudaGetSymbolAddress((void**)&eoff,     g_eoff);
    cudaGetSymbolAddress((void**)&partials, g_partials);
    cudaGetSymbolAddress((void**)&edges,    g_edges);

    const int T = 256;

    // CSR build + fp16 conversion of x. (counts is zero at entry; scan restores it.)
    hist_kernel<<<(n_edges + T - 1) / T, T>>>(adj_row, counts, eoff, n_edges);
    const int nconv = N_NODES * NH4;
    conv_kernel<<<(nconv + T - 1) / T, T>>>((const float4*)x, xh, nconv);

    scan_block_kernel<<<SCAN_BLOCKS, SCAN_CHUNK>>>(counts, row_ptr, partials);

    scatter_kernel<<<(n_edges + T - 1) / T, T>>>(adj_row, adj_col, adj_vals,
                                                 row_ptr, partials, eoff, edges, n_edges);

    // Two propagation rounds.
    const int WPB = T / 32;
    const int sb = (N_NODES + WPB - 1) / WPB;
    spmm_csr_h_kernel<1><<<sb, T>>>(xh, row_ptr, partials, edges, scratchh);
    spmm_csr_h_kernel<0><<<sb, T>>>(scratchh, row_ptr, partials, edges, out);
}

// round 11
// speedup vs baseline: 1.4008x; 1.0291x over previous
#include <cuda_runtime.h>
#include <cuda_fp16.h>
#include <cstdint>

#define N_NODES 50000
#define N_EDGES 1600000
#define D_FEAT  128
#define NH4     (D_FEAT / 8)   // 16 uint4 (8 halfs) per fp16 row

#define SCAN_CHUNK   1024
#define SCAN_BLOCKS  ((N_NODES + SCAN_CHUNK - 1) / SCAN_CHUNK)   // 49

// Scratch (no cudaMalloc allowed).
__device__ uint4 g_xh      [(size_t)N_NODES * NH4];   // fp16 copy of gather operand
__device__ uint4 g_scratchh[(size_t)N_NODES * NH4];   // fp16 round-1 result
__device__ int   g_counts  [N_NODES];                 // zero at every call entry
__device__ int   g_row_ptr [N_NODES + 1];             // chunk-local exclusive scan
__device__ int   g_eoff    [N_EDGES];
__device__ int2  g_edges   [N_EDGES];                 // packed (col, val-bits)
__device__ int   g_partials[SCAN_BLOCKS];             // per-chunk totals

// ---- per-block inline exclusive scan of the 49 chunk totals into SMEM ------
__device__ __forceinline__ void block_scan_partials(
    const int* __restrict__ partials, int* s_poffs, int* s_wsum)
{
    const int tid = threadIdx.x;
    int p_incl = 0, p_v = 0;
    if (tid < 64) {
        const int lane = tid & 31;
        p_v = (tid < SCAN_BLOCKS) ? __ldg(partials + tid) : 0;
        p_incl = p_v;
        #pragma unroll
        for (int off = 1; off < 32; off <<= 1) {
            int t = __shfl_up_sync(0xffffffffu, p_incl, off);
            if (lane >= off) p_incl += t;
        }
        if (lane == 31) s_wsum[tid >> 5] = p_incl;
    }
    __syncthreads();
    if (tid < SCAN_BLOCKS) {
        int wadd = (tid >= 32) ? s_wsum[0] : 0;
        s_poffs[tid] = p_incl - p_v + wadd;
    }
    __syncthreads();
}

// ---------------- fp32 -> fp16 conversion (8 feats / thread) ----------------
__global__ void conv_kernel(const float4* __restrict__ in, uint4* __restrict__ out, int n) {
    int i = blockIdx.x * blockDim.x + threadIdx.x;
    if (i >= n) return;
    float4 f0 = in[2 * i];
    float4 f1 = in[2 * i + 1];
    __half2 h0 = __float22half2_rn(make_float2(f0.x, f0.y));
    __half2 h1 = __float22half2_rn(make_float2(f0.z, f0.w));
    __half2 h2 = __float22half2_rn(make_float2(f1.x, f1.y));
    __half2 h3 = __float22half2_rn(make_float2(f1.z, f1.w));
    uint4 o;
    o.x = *reinterpret_cast<unsigned*>(&h0);
    o.y = *reinterpret_cast<unsigned*>(&h1);
    o.z = *reinterpret_cast<unsigned*>(&h2);
    o.w = *reinterpret_cast<unsigned*>(&h3);
    out[i] = o;
}

// ---------------- CSR build ----------------
// Histogram + per-edge rank, 4 edges per thread (MLP=4 on the atomics).
__global__ void hist_kernel(const int4* __restrict__ adj_row4, int* __restrict__ counts,
                            int4* __restrict__ eoff4, int n_q, int n_edges,
                            const int* __restrict__ adj_row, int* __restrict__ eoff) {
    int q = blockIdx.x * blockDim.x + threadIdx.x;
    if (q < n_q) {
        int4 r = __ldg(adj_row4 + q);
        int4 o;
        o.x = atomicAdd(&counts[r.x], 1);
        o.y = atomicAdd(&counts[r.y], 1);
        o.z = atomicAdd(&counts[r.z], 1);
        o.w = atomicAdd(&counts[r.w], 1);
        eoff4[q] = o;
    } else if (q == n_q) {            // tail (n_edges % 4 != 0)
        for (int e = n_q * 4; e < n_edges; e++)
            eoff[e] = atomicAdd(&counts[adj_row[e]], 1);
    }
}

// Chunk-local exclusive scan; restores counts to zero; writes row_ptr[N] too.
__global__ void __launch_bounds__(1024) scan_block_kernel(
    int* __restrict__ counts, int* __restrict__ row_ptr,
    int* __restrict__ partials)
{
    __shared__ int warp_sums[32];
    const int tid  = threadIdx.x;
    const int lane = tid & 31;
    const int wid  = tid >> 5;
    const int i    = blockIdx.x * SCAN_CHUNK + tid;

    int v = 0;
    if (i < N_NODES) {
        v = counts[i];
        counts[i] = 0;          // restore invariant
    }

    int incl = v;
    #pragma unroll
    for (int off = 1; off < 32; off <<= 1) {
        int t = __shfl_up_sync(0xffffffffu, incl, off);
        if (lane >= off) incl += t;
    }
    if (lane == 31) warp_sums[wid] = incl;
    __syncthreads();

    if (wid == 0) {
        int s = warp_sums[lane];
        int si = s;
        #pragma unroll
        for (int off = 1; off < 32; off <<= 1) {
            int t = __shfl_up_sync(0xffffffffu, si, off);
            if (lane >= off) si += t;
        }
        warp_sums[lane] = si - s;
    }
    __syncthreads();

    int excl = incl - v + warp_sums[wid];
    if (i <= N_NODES) row_ptr[i] = excl;                // includes i == N_NODES
    if (tid == SCAN_CHUNK - 1) partials[blockIdx.x] = excl + v;
}

// Place packed (col, val), 4 edges per thread (MLP=4 on random accesses).
__global__ void __launch_bounds__(256) scatter_kernel(
    const int4* __restrict__ adj_row4,
    const int4* __restrict__ adj_col4,
    const float4* __restrict__ adj_vals4,
    const int* __restrict__ row_ptr,
    const int* __restrict__ partials,
    const int4* __restrict__ eoff4,
    int2* __restrict__ edges,
    int n_q, int n_edges,
    const int* __restrict__ adj_row,
    const int* __restrict__ adj_col,
    const float* __restrict__ adj_vals,
    const int* __restrict__ eoff)
{
    __shared__ int s_poffs[SCAN_BLOCKS];
    __shared__ int s_wsum[2];
    block_scan_partials(partials, s_poffs, s_wsum);

    int q = blockIdx.x * blockDim.x + threadIdx.x;
    if (q < n_q) {
        int4   r = __ldg(adj_row4  + q);
        int4   c = __ldg(adj_col4  + q);
        float4 v = __ldg(adj_vals4 + q);
        int4   o = __ldg(eoff4     + q);
        int b0 = __ldg(row_ptr + r.x);
        int b1 = __ldg(row_ptr + r.y);
        int b2 = __ldg(row_ptr + r.z);
        int b3 = __ldg(row_ptr + r.w);
        edges[b0 + s_poffs[r.x >> 10] + o.x] = make_int2(c.x, __float_as_int(v.x));
        edges[b1 + s_poffs[r.y >> 10] + o.y] = make_int2(c.y, __float_as_int(v.y));
        edges[b2 + s_poffs[r.z >> 10] + o.z] = make_int2(c.z, __float_as_int(v.z));
        edges[b3 + s_poffs[r.w >> 10] + o.w] = make_int2(c.w, __float_as_int(v.w));
    } else if (q == n_q) {            // tail
        for (int e = n_q * 4; e < n_edges; e++) {
            int r = adj_row[e];
            int p = __ldg(row_ptr + r) + s_poffs[r >> 10] + eoff[e];
            edges[p] = make_int2(adj_col[e], __float_as_int(adj_vals[e]));
        }
    }
}

// ---------------- CSR SpMM: warp/row, half-warp/edge, fp16 gather ------------
template <int OUT_HALF>
__global__ void __launch_bounds__(256) spmm_csr_h_kernel(
    const uint4* __restrict__ xh,
    const int*   __restrict__ row_ptr,
    const int*   __restrict__ partials,
    const int2*  __restrict__ edges,
    void*        __restrict__ out)
{
    __shared__ int s_poffs[SCAN_BLOCKS];
    __shared__ int s_wsum[2];
    block_scan_partials(partials, s_poffs, s_wsum);

    int row  = (blockIdx.x * blockDim.x + threadIdx.x) >> 5;
    int lane = threadIdx.x & 31;
    if (row >= N_NODES) return;

    const int hlane = lane & 15;
    const int half  = lane >> 4;

    int start = __ldg(row_ptr + row)     + s_poffs[row >> 10];
    int end   = __ldg(row_ptr + row + 1) + s_poffs[(row + 1) >> 10];

    float acc[8] = {0.f, 0.f, 0.f, 0.f, 0.f, 0.f, 0.f, 0.f};

    for (int base = start; base < end; base += 32) {
        int n = end - base;
        if (n > 32) n = 32;
        int2 ep = make_int2(0, 0);
        if (lane < n) ep = __ldg(edges + base + lane);

        #pragma unroll 4
        for (int j = 0; j < n; j += 2) {
            int je = j + half;
            int cj = __shfl_sync(0xffffffffu, ep.x, je);
            int vb = __shfl_sync(0xffffffffu, ep.y, je);
            if (je >= n) { cj = 0; vb = 0; }
            float vj = __int_as_float(vb);

            uint4 m = __ldg(xh + (size_t)cj * NH4 + hlane);
            __half2 h0 = *reinterpret_cast<__half2*>(&m.x);
            __half2 h1 = *reinterpret_cast<__half2*>(&m.y);
            __half2 h2 = *reinterpret_cast<__half2*>(&m.z);
            __half2 h3 = *reinterpret_cast<__half2*>(&m.w);
            float2 f0 = __half22float2(h0);
            float2 f1 = __half22float2(h1);
            float2 f2 = __half22float2(h2);
            float2 f3 = __half22float2(h3);
            acc[0] = fmaf(vj, f0.x, acc[0]);
            acc[1] = fmaf(vj, f0.y, acc[1]);
            acc[2] = fmaf(vj, f1.x, acc[2]);
            acc[3] = fmaf(vj, f1.y, acc[3]);
            acc[4] = fmaf(vj, f2.x, acc[4]);
            acc[5] = fmaf(vj, f2.y, acc[5]);
            acc[6] = fmaf(vj, f3.x, acc[6]);
            acc[7] = fmaf(vj, f3.y, acc[7]);
        }
    }

    #pragma unroll
    for (int k = 0; k < 8; k++)
        acc[k] += __shfl_xor_sync(0xffffffffu, acc[k], 16);

    if (half == 0) {
        if (OUT_HALF) {
            __half2 h0 = __float22half2_rn(make_float2(acc[0], acc[1]));
            __half2 h1 = __float22half2_rn(make_float2(acc[2], acc[3]));
            __half2 h2 = __float22half2_rn(make_float2(acc[4], acc[5]));
            __half2 h3 = __float22half2_rn(make_float2(acc[6], acc[7]));
            uint4 o;
            o.x = *reinterpret_cast<unsigned*>(&h0);
            o.y = *reinterpret_cast<unsigned*>(&h1);
            o.z = *reinterpret_cast<unsigned*>(&h2);
            o.w = *reinterpret_cast<unsigned*>(&h3);
            reinterpret_cast<uint4*>(out)[(size_t)row * NH4 + hlane] = o;
        } else {
            float4* o4 = reinterpret_cast<float4*>(out) + (size_t)row * (D_FEAT / 4) + hlane * 2;
            o4[0] = make_float4(acc[0], acc[1], acc[2], acc[3]);
            o4[1] = make_float4(acc[4], acc[5], acc[6], acc[7]);
        }
    }
}

// ---------------- launch ----------------
extern "C" void kernel_launch(void* const* d_in, const int* in_sizes, int n_in,
                              void* d_out, int out_size) {
    const float* x        = (const float*)d_in[0];
    const int*   adj_row  = (const int*)  d_in[1];
    const int*   adj_col  = (const int*)  d_in[2];
    const float* adj_vals = (const float*)d_in[3];
    float*       out      = (float*)d_out;

    int n_edges = in_sizes[1];
    int n_q = n_edges / 4;             // int4 quads

    uint4 *xh, *scratchh; int *counts, *row_ptr, *eoff, *partials; int2 *edges;
    cudaGetSymbolAddress((void**)&xh,       g_xh);
    cudaGetSymbolAddress((void**)&scratchh, g_scratchh);
    cudaGetSymbolAddress((void**)&counts,   g_counts);
    cudaGetSymbolAddress((void**)&row_ptr,  g_row_ptr);
    cudaGetSymbolAddress((void**)&eoff,     g_eoff);
    cudaGetSymbolAddress((void**)&partials, g_partials);
    cudaGetSymbolAddress((void**)&edges,    g_edges);

    const int T = 256;
    const int hb = (n_q + 1 + T - 1) / T;   // +1 thread for the tail

    // CSR build + fp16 conversion of x. (counts zero at entry; scan restores it.)
    hist_kernel<<<hb, T>>>((const int4*)adj_row, counts, (int4*)eoff,
                           n_q, n_edges, adj_row, eoff);
    const int nconv = N_NODES * NH4;
    conv_kernel<<<(nconv + T - 1) / T, T>>>((const float4*)x, xh, nconv);

    scan_block_kernel<<<SCAN_BLOCKS, SCAN_CHUNK>>>(counts, row_ptr, partials);

    scatter_kernel<<<hb, T>>>((const int4*)adj_row, (const int4*)adj_col,
                              (const float4*)adj_vals, row_ptr, partials,
                              (const int4*)eoff, edges, n_q, n_edges,
                              adj_row, adj_col, adj_vals, eoff);

    // Two propagation rounds.
    const int WPB = T / 32;
    const int sb = (N_NODES + WPB - 1) / WPB;
    spmm_csr_h_kernel<1><<<sb, T>>>(xh, row_ptr, partials, edges, scratchh);
    spmm_csr_h_kernel<0><<<sb, T>>>(scratchh, row_ptr, partials, edges, out);
}

// round 13
// speedup vs baseline: 1.4011x; 1.0003x over previous
#include <cuda_runtime.h>
#include <cuda_fp16.h>
#include <cstdint>

#define N_NODES 50000
#define N_EDGES 1600000
#define D_FEAT  128
#define NH4     (D_FEAT / 8)   // 16 uint4 (8 halfs) per fp16 row

#define SCAN_CHUNK   1024
#define SCAN_BLOCKS  ((N_NODES + SCAN_CHUNK - 1) / SCAN_CHUNK)   // 49

// Scratch (no cudaMalloc allowed).
__device__ uint4 g_xh      [(size_t)N_NODES * NH4];   // fp16 copy of gather operand
__device__ uint4 g_scratchh[(size_t)N_NODES * NH4];   // fp16 round-1 result
__device__ int   g_counts  [N_NODES];                 // zero at every call entry
__device__ int   g_row_ptr [N_NODES + 1];             // chunk-local exclusive scan
__device__ int   g_cursor  [N_NODES];                 // chunk-local, consumed by scatter
__device__ int2  g_edges   [N_EDGES];                 // packed (col, val-bits)
__device__ int   g_partials[SCAN_BLOCKS];             // per-chunk totals

// ---- per-block inline exclusive scan of the 49 chunk totals into SMEM ------
__device__ __forceinline__ void block_scan_partials(
    const int* __restrict__ partials, int* s_poffs, int* s_wsum)
{
    const int tid = threadIdx.x;
    int p_incl = 0, p_v = 0;
    if (tid < 64) {
        const int lane = tid & 31;
        p_v = (tid < SCAN_BLOCKS) ? __ldg(partials + tid) : 0;
        p_incl = p_v;
        #pragma unroll
        for (int off = 1; off < 32; off <<= 1) {
            int t = __shfl_up_sync(0xffffffffu, p_incl, off);
            if (lane >= off) p_incl += t;
        }
        if (lane == 31) s_wsum[tid >> 5] = p_incl;
    }
    __syncthreads();
    if (tid < SCAN_BLOCKS) {
        int wadd = (tid >= 32) ? s_wsum[0] : 0;
        s_poffs[tid] = p_incl - p_v + wadd;
    }
    __syncthreads();
}

// -------- fused hist + fp32->fp16 conversion (independent work, one launch) --
// Blocks [0, histB): histogram RED (4 edges/thread, no return value).
// Blocks [histB, histB+convB): convert 8 feats/thread.
__global__ void __launch_bounds__(256) hist_conv_kernel(
    const int4* __restrict__ adj_row4, int* __restrict__ counts,
    int n_q, int n_edges, const int* __restrict__ adj_row,
    int histB,
    const float4* __restrict__ xin, uint4* __restrict__ xh, int nconv)
{
    if ((int)blockIdx.x < histB) {
        int q = blockIdx.x * blockDim.x + threadIdx.x;
        if (q < n_q) {
            int4 r = __ldg(adj_row4 + q);
            atomicAdd(&counts[r.x], 1);     // no return -> RED
            atomicAdd(&counts[r.y], 1);
            atomicAdd(&counts[r.z], 1);
            atomicAdd(&counts[r.w], 1);
        } else if (q == n_q) {              // tail (n_edges % 4 != 0)
            for (int e = n_q * 4; e < n_edges; e++)
                atomicAdd(&counts[adj_row[e]], 1);
        }
    } else {
        int i = (blockIdx.x - histB) * blockDim.x + threadIdx.x;
        if (i >= nconv) return;
        float4 f0 = xin[2 * i];
        float4 f1 = xin[2 * i + 1];
        __half2 h0 = __float22half2_rn(make_float2(f0.x, f0.y));
        __half2 h1 = __float22half2_rn(make_float2(f0.z, f0.w));
        __half2 h2 = __float22half2_rn(make_float2(f1.x, f1.y));
        __half2 h3 = __float22half2_rn(make_float2(f1.z, f1.w));
        uint4 o;
        o.x = *reinterpret_cast<unsigned*>(&h0);
        o.y = *reinterpret_cast<unsigned*>(&h1);
        o.z = *reinterpret_cast<unsigned*>(&h2);
        o.w = *reinterpret_cast<unsigned*>(&h3);
        xh[i] = o;
    }
}

// Chunk-local exclusive scan; restores counts to zero; writes row_ptr, cursor.
__global__ void __launch_bounds__(1024) scan_block_kernel(
    int* __restrict__ counts, int* __restrict__ row_ptr,
    int* __restrict__ cursor, int* __restrict__ partials)
{
    __shared__ int warp_sums[32];
    const int tid  = threadIdx.x;
    const int lane = tid & 31;
    const int wid  = tid >> 5;
    const int i    = blockIdx.x * SCAN_CHUNK + tid;

    int v = 0;
    if (i < N_NODES) {
        v = counts[i];
        counts[i] = 0;          // restore invariant
    }

    int incl = v;
    #pragma unroll
    for (int off = 1; off < 32; off <<= 1) {
        int t = __shfl_up_sync(0xffffffffu, incl, off);
        if (lane >= off) incl += t;
    }
    if (lane == 31) warp_sums[wid] = incl;
    __syncthreads();

    if (wid == 0) {
        int s = warp_sums[lane];
        int si = s;
        #pragma unroll
        for (int off = 1; off < 32; off <<= 1) {
            int t = __shfl_up_sync(0xffffffffu, si, off);
            if (lane >= off) si += t;
        }
        warp_sums[lane] = si - s;
    }
    __syncthreads();

    int excl = incl - v + warp_sums[wid];
    if (i <= N_NODES) row_ptr[i] = excl;                // includes i == N_NODES
    if (i < N_NODES)  cursor[i]  = excl;                // scatter's working copy
    if (tid == SCAN_CHUNK - 1) partials[blockIdx.x] = excl + v;
}

// Place packed (col, val). Slot from cursor atomic (chunk-local) + s_poffs.
__global__ void __launch_bounds__(256) scatter_kernel(
    const int4* __restrict__ adj_row4,
    const int4* __restrict__ adj_col4,
    const float4* __restrict__ adj_vals4,
    int* __restrict__ cursor,
    const int* __restrict__ partials,
    int2* __restrict__ edges,
    int n_q, int n_edges,
    const int* __restrict__ adj_row,
    const int* __restrict__ adj_col,
    const float* __restrict__ adj_vals)
{
    __shared__ int s_poffs[SCAN_BLOCKS];
    __shared__ int s_wsum[2];
    block_scan_partials(partials, s_poffs, s_wsum);

    int q = blockIdx.x * blockDim.x + threadIdx.x;
    if (q < n_q) {
        int4   r = __ldg(adj_row4  + q);
        int4   c = __ldg(adj_col4  + q);
        float4 v = __ldg(adj_vals4 + q);
        int p0 = atomicAdd(&cursor[r.x], 1);
        int p1 = atomicAdd(&cursor[r.y], 1);
        int p2 = atomicAdd(&cursor[r.z], 1);
        int p3 = atomicAdd(&cursor[r.w], 1);
        edges[p0 + s_poffs[r.x >> 10]] = make_int2(c.x, __float_as_int(v.x));
        edges[p1 + s_poffs[r.y >> 10]] = make_int2(c.y, __float_as_int(v.y));
        edges[p2 + s_poffs[r.z >> 10]] = make_int2(c.z, __float_as_int(v.z));
        edges[p3 + s_poffs[r.w >> 10]] = make_int2(c.w, __float_as_int(v.w));
    } else if (q == n_q) {            // tail
        for (int e = n_q * 4; e < n_edges; e++) {
            int r = adj_row[e];
            int p = atomicAdd(&cursor[r], 1) + s_poffs[r >> 10];
            edges[p] = make_int2(adj_col[e], __float_as_int(adj_vals[e]));
        }
    }
}

// ---------------- CSR SpMM: warp/row, half-warp/edge, fp16 gather ------------
template <int OUT_HALF>
__global__ void __launch_bounds__(256) spmm_csr_h_kernel(
    const uint4* __restrict__ xh,
    const int*   __restrict__ row_ptr,
    const int*   __restrict__ partials,
    const int2*  __restrict__ edges,
    void*        __restrict__ out)
{
    __shared__ int s_poffs[SCAN_BLOCKS];
    __shared__ int s_wsum[2];
    block_scan_partials(partials, s_poffs, s_wsum);

    int row  = (blockIdx.x * blockDim.x + threadIdx.x) >> 5;
    int lane = threadIdx.x & 31;
    if (row >= N_NODES) return;

    const int hlane = lane & 15;
    const int half  = lane >> 4;

    int start = __ldg(row_ptr + row)     + s_poffs[row >> 10];
    int end   = __ldg(row_ptr + row + 1) + s_poffs[(row + 1) >> 10];

    float acc[8] = {0.f, 0.f, 0.f, 0.f, 0.f, 0.f, 0.f, 0.f};

    for (int base = start; base < end; base += 32) {
        int n = end - base;
        if (n > 32) n = 32;
        int2 ep = make_int2(0, 0);
        if (lane < n) ep = __ldg(edges + base + lane);

        #pragma unroll 4
        for (int j = 0; j < n; j += 2) {
            int je = j + half;
            int cj = __shfl_sync(0xffffffffu, ep.x, je);
            int vb = __shfl_sync(0xffffffffu, ep.y, je);
            if (je >= n) { cj = 0; vb = 0; }
            float vj = __int_as_float(vb);

            uint4 m = __ldg(xh + (size_t)cj * NH4 + hlane);
            __half2 h0 = *reinterpret_cast<__half2*>(&m.x);
            __half2 h1 = *reinterpret_cast<__half2*>(&m.y);
            __half2 h2 = *reinterpret_cast<__half2*>(&m.z);
            __half2 h3 = *reinterpret_cast<__half2*>(&m.w);
            float2 f0 = __half22float2(h0);
            float2 f1 = __half22float2(h1);
            float2 f2 = __half22float2(h2);
            float2 f3 = __half22float2(h3);
            acc[0] = fmaf(vj, f0.x, acc[0]);
            acc[1] = fmaf(vj, f0.y, acc[1]);
            acc[2] = fmaf(vj, f1.x, acc[2]);
            acc[3] = fmaf(vj, f1.y, acc[3]);
            acc[4] = fmaf(vj, f2.x, acc[4]);
            acc[5] = fmaf(vj, f2.y, acc[5]);
            acc[6] = fmaf(vj, f3.x, acc[6]);
            acc[7] = fmaf(vj, f3.y, acc[7]);
        }
    }

    #pragma unroll
    for (int k = 0; k < 8; k++)
        acc[k] += __shfl_xor_sync(0xffffffffu, acc[k], 16);

    if (half == 0) {
        if (OUT_HALF) {
            __half2 h0 = __float22half2_rn(make_float2(acc[0], acc[1]));
            __half2 h1 = __float22half2_rn(make_float2(acc[2], acc[3]));
            __half2 h2 = __float22half2_rn(make_float2(acc[4], acc[5]));
            __half2 h3 = __float22half2_rn(make_float2(acc[6], acc[7]));
            uint4 o;
            o.x = *reinterpret_cast<unsigned*>(&h0);
            o.y = *reinterpret_cast<unsigned*>(&h1);
            o.z = *reinterpret_cast<unsigned*>(&h2);
            o.w = *reinterpret_cast<unsigned*>(&h3);
            reinterpret_cast<uint4*>(out)[(size_t)row * NH4 + hlane] = o;
        } else {
            float4* o4 = reinterpret_cast<float4*>(out) + (size_t)row * (D_FEAT / 4) + hlane * 2;
            o4[0] = make_float4(acc[0], acc[1], acc[2], acc[3]);
            o4[1] = make_float4(acc[4], acc[5], acc[6], acc[7]);
        }
    }
}

// ---------------- launch ----------------
extern "C" void kernel_launch(void* const* d_in, const int* in_sizes, int n_in,
                              void* d_out, int out_size) {
    const float* x        = (const float*)d_in[0];
    const int*   adj_row  = (const int*)  d_in[1];
    const int*   adj_col  = (const int*)  d_in[2];
    const float* adj_vals = (const float*)d_in[3];
    float*       out      = (float*)d_out;

    int n_edges = in_sizes[1];
    int n_q = n_edges / 4;             // int4 quads

    uint4 *xh, *scratchh; int *counts, *row_ptr, *cursor, *partials; int2 *edges;
    cudaGetSymbolAddress((void**)&xh,       g_xh);
    cudaGetSymbolAddress((void**)&scratchh, g_scratchh);
    cudaGetSymbolAddress((void**)&counts,   g_counts);
    cudaGetSymbolAddress((void**)&row_ptr,  g_row_ptr);
    cudaGetSymbolAddress((void**)&cursor,   g_cursor);
    cudaGetSymbolAddress((void**)&partials, g_partials);
    cudaGetSymbolAddress((void**)&edges,    g_edges);

    const int T = 256;
    const int histB = (n_q + 1 + T - 1) / T;   // +1 thread for the tail
    const int nconv = N_NODES * NH4;
    const int convB = (nconv + T - 1) / T;

    // Fused: histogram (RED) + fp16 conversion. counts zero at entry.
    hist_conv_kernel<<<histB + convB, T>>>((const int4*)adj_row, counts,
                                           n_q, n_edges, adj_row, histB,
                                           (const float4*)x, xh, nconv);

    scan_block_kernel<<<SCAN_BLOCKS, SCAN_CHUNK>>>(counts, row_ptr, cursor, partials);

    scatter_kernel<<<histB, T>>>((const int4*)adj_row, (const int4*)adj_col,
                                 (const float4*)adj_vals, cursor, partials,
                                 edges, n_q, n_edges,
                                 adj_row, adj_col, adj_vals);

    // Two propagation rounds.
    const int WPB = T / 32;
    const int sb = (N_NODES + WPB - 1) / WPB;
    spmm_csr_h_kernel<1><<<sb, T>>>(xh, row_ptr, partials, edges, scratchh);
    spmm_csr_h_kernel<0><<<sb, T>>>(scratchh, row_ptr, partials, edges, out);
}